// round 1
// baseline (speedup 1.0000x reference)
#include <cuda_runtime.h>
#include <math.h>

#define BATCH 96
#define NQ 196     // image tokens
#define NR 77      // text tokens
#define DIM 512
#define KC 32      // K-chunk
#define LDA 209    // padded 208 rows + 1 (209 mod 32 = 17, gcd(17,32)=1 -> conflict-free)
#define LDB 81     // padded 80 cols + 1  (81 mod 32 = 17)
#define RI 13      // rows per thread (16 row-threads * 13 = 208 >= 196)
#define RJ 10      // cols per thread (8 col-threads * 10 = 80 >= 77)

// scratch logit matrices (device globals: no allocation allowed)
__device__ float g_i2t[BATCH * BATCH];
__device__ float g_t2i[BATCH * BATCH];

// One CTA per (image b, text c) pair: computes the 196x77 score tile
// S[q][r] = <img[b,q,:], txt[c,r,:]> and reduces:
//   i2t[b][c] = mean_q max_r S
//   t2i[c][b] = mean_r max_q S
__global__ __launch_bounds__(128, 2) void fg_pair_kernel(
    const float* __restrict__ img, const float* __restrict__ txt)
{
    __shared__ float As[KC * LDA];   // As[k][q], zero-padded rows 196..207
    __shared__ float Bs[KC * LDB];   // Bs[k][r], zero-padded cols 77..79
    __shared__ float ws1[4], ws2[4];

    const int tid = threadIdx.x;
    const int tx = tid & 7;    // col-thread 0..7
    const int ty = tid >> 3;   // row-thread 0..15

    const int bi = blockIdx.x / BATCH;  // image index
    const int bc = blockIdx.x % BATCH;  // text index

    const float* Ag = img + (size_t)bi * NQ * DIM;
    const float* Bg = txt + (size_t)bc * NR * DIM;

    float acc[RI][RJ];
#pragma unroll
    for (int i = 0; i < RI; i++)
#pragma unroll
        for (int j = 0; j < RJ; j++) acc[i][j] = 0.0f;

    const int kf = tid & 7;    // float4 slot within K-chunk (k = 4*kf..4*kf+3)
    const int qr = tid >> 3;   // row base 0..15

    for (int k0 = 0; k0 < DIM; k0 += KC) {
        // ---- stage A chunk: 208 rows x 32 k (transposed to k-major) ----
#pragma unroll
        for (int p = 0; p < 13; ++p) {
            int q = qr + 16 * p;             // 0..207
            float4 v = make_float4(0.f, 0.f, 0.f, 0.f);
            if (q < NQ) v = *(const float4*)(Ag + (size_t)q * DIM + k0 + kf * 4);
            As[(kf * 4 + 0) * LDA + q] = v.x;
            As[(kf * 4 + 1) * LDA + q] = v.y;
            As[(kf * 4 + 2) * LDA + q] = v.z;
            As[(kf * 4 + 3) * LDA + q] = v.w;
        }
        // ---- stage B chunk: 80 rows x 32 k ----
#pragma unroll
        for (int p = 0; p < 5; ++p) {
            int r = qr + 16 * p;             // 0..79
            float4 v = make_float4(0.f, 0.f, 0.f, 0.f);
            if (r < NR) v = *(const float4*)(Bg + (size_t)r * DIM + k0 + kf * 4);
            Bs[(kf * 4 + 0) * LDB + r] = v.x;
            Bs[(kf * 4 + 1) * LDB + r] = v.y;
            Bs[(kf * 4 + 2) * LDB + r] = v.z;
            Bs[(kf * 4 + 3) * LDB + r] = v.w;
        }
        __syncthreads();

        // ---- register-tiled FFMA ----
#pragma unroll 8
        for (int kk = 0; kk < KC; ++kk) {
            float a[RI], bb[RJ];
#pragma unroll
            for (int i = 0; i < RI; i++) a[i] = As[kk * LDA + ty + 16 * i];
#pragma unroll
            for (int j = 0; j < RJ; j++) bb[j] = Bs[kk * LDB + tx + 8 * j];
#pragma unroll
            for (int i = 0; i < RI; i++)
#pragma unroll
                for (int j = 0; j < RJ; j++)
                    acc[i][j] = fmaf(a[i], bb[j], acc[i][j]);
        }
        __syncthreads();
    }

    // ---- reductions: reuse As as scratch ----
    // red[q*8+tx]   : per-thread max over its cols for row q     (196*8 floats)
    // red2[r*16+ty] : per-thread max over its rows for col r     (77*16 floats)
    float* red  = As;
    float* red2 = As + 1600;

#pragma unroll
    for (int i = 0; i < RI; i++) {
        int q = ty + 16 * i;
        if (q < NQ) {
            float m = -INFINITY;
#pragma unroll
            for (int j = 0; j < RJ; j++)
                if (tx + 8 * j < NR) m = fmaxf(m, acc[i][j]);
            red[q * 8 + tx] = m;
        }
    }
#pragma unroll
    for (int j = 0; j < RJ; j++) {
        int r = tx + 8 * j;
        if (r < NR) {
            float m = -INFINITY;
#pragma unroll
            for (int i = 0; i < RI; i++)
                if (ty + 16 * i < NQ) m = fmaxf(m, acc[i][j]);
            red2[r * 16 + ty] = m;
        }
    }
    __syncthreads();

    float s1 = 0.0f;  // sum over q of rowmax
    for (int q = tid; q < NQ; q += 128) {
        float m = red[q * 8];
#pragma unroll
        for (int t = 1; t < 8; t++) m = fmaxf(m, red[q * 8 + t]);
        s1 += m;
    }
    float s2 = 0.0f;  // sum over r of colmax
    for (int r = tid; r < NR; r += 128) {
        float m = red2[r * 16];
#pragma unroll
        for (int t = 1; t < 16; t++) m = fmaxf(m, red2[r * 16 + t]);
        s2 += m;
    }

    // block reduce (4 warps)
#pragma unroll
    for (int off = 16; off > 0; off >>= 1) {
        s1 += __shfl_down_sync(0xFFFFFFFFu, s1, off);
        s2 += __shfl_down_sync(0xFFFFFFFFu, s2, off);
    }
    if ((tid & 31) == 0) { ws1[tid >> 5] = s1; ws2[tid >> 5] = s2; }
    __syncthreads();
    if (tid == 0) {
        float r1 = ws1[0] + ws1[1] + ws1[2] + ws1[3];
        float r2 = ws2[0] + ws2[1] + ws2[2] + ws2[3];
        g_i2t[bi * BATCH + bc] = r1 * (1.0f / NQ);
        g_t2i[bc * BATCH + bi] = r2 * (1.0f / NR);
    }
}

// CE with arange labels on both 96x96 logit matrices; writes the scalar loss.
__global__ void fg_loss_kernel(float* __restrict__ out)
{
    __shared__ float sred[192];
    const int t = threadIdx.x;   // 0..191
    float contrib = 0.0f;
    if (t < 2 * BATCH) {
        const int b = (t < BATCH) ? t : (t - BATCH);
        const float* row = (t < BATCH) ? &g_i2t[b * BATCH] : &g_t2i[b * BATCH];
        float m = -INFINITY;
        for (int i = 0; i < BATCH; i++) m = fmaxf(m, row[i]);
        float s = 0.0f;
        for (int i = 0; i < BATCH; i++) s += expf(row[i] - m);
        float lse = m + logf(s);
        contrib = lse - row[b];
    }
    sred[t] = contrib;
    __syncthreads();
    if (t == 0) {
        float s = 0.0f;
        for (int i = 0; i < 2 * BATCH; i++) s += sred[i];
        out[0] = s * (0.5f / BATCH);
    }
}

extern "C" void kernel_launch(void* const* d_in, const int* in_sizes, int n_in,
                              void* d_out, int out_size)
{
    // image_out (96*196*512 = 9,633,792) vs text_out (96*77*512 = 3,784,704):
    // pick by size to be robust to metadata ordering.
    const float* img;
    const float* txt;
    if (in_sizes[0] > in_sizes[1]) {
        img = (const float*)d_in[0];
        txt = (const float*)d_in[1];
    } else {
        img = (const float*)d_in[1];
        txt = (const float*)d_in[0];
    }
    float* out = (float*)d_out;

    fg_pair_kernel<<<BATCH * BATCH, 128>>>(img, txt);
    fg_loss_kernel<<<1, 192>>>(out);
}

// round 5
// speedup vs baseline: 1.8913x; 1.8913x over previous
#include <cuda_runtime.h>
#include <cstdint>
#include <math.h>

#define BATCH 96
#define NQ 196
#define NR 77
#define DIM 512
#define KC 16                  // floats per k-chunk (64 B per row)
#define NCHUNK (DIM / KC)      // 32
#define G 4                    // texts per CTA
#define NGR (BATCH / G)        // 24
#define NPAD 80
#define NTILE (G * NPAD)       // 320
#define ROWB 80                // padded row stride in bytes (64 data + 16 pad)

// ---------------- device scratch ----------------
__device__ float g_img_hi[BATCH * NQ * DIM];
__device__ float g_img_lo[BATCH * NQ * DIM];
__device__ float g_txt_hi[BATCH * NR * DIM];
__device__ float g_txt_lo[BATCH * NR * DIM];
__device__ float g_rowsum_part[2 * BATCH * BATCH];          // [mtile][b][c]
__device__ float g_colmax_part[2 * BATCH * BATCH * NPAD];   // [mtile][c][b][r]
__device__ float g_i2t[BATCH * BATCH];
__device__ float g_t2i[BATCH * BATCH];
__device__ float g_contrib[2 * BATCH];

// ---------------- PTX helpers (base sm_103 ISA only) ----------------
__device__ __forceinline__ uint32_t smem_u32(const void* p) {
    uint32_t a;
    asm("{ .reg .u64 t; cvta.to.shared.u64 t, %1; cvt.u32.u64 %0, t; }" : "=r"(a) : "l"(p));
    return a;
}
#define CP_ASYNC16(sa, gp, sz) \
    asm volatile("cp.async.cg.shared.global [%0], [%1], 16, %2;" \
        :: "r"(sa), "l"(gp), "r"(sz) : "memory")
#define CP_COMMIT()  asm volatile("cp.async.commit_group;" ::: "memory")
#define CP_WAIT2()   asm volatile("cp.async.wait_group 2;" ::: "memory")

#define LDSM_X4(r0, r1, r2, r3, a) \
    asm volatile("ldmatrix.sync.aligned.m8n8.x4.shared.b16 {%0,%1,%2,%3}, [%4];" \
        : "=r"(r0), "=r"(r1), "=r"(r2), "=r"(r3) : "r"(a))

#define MMA_TF32(d, a0, a1, a2, a3, b0, b1) \
    asm volatile("mma.sync.aligned.m16n8k8.row.col.f32.tf32.tf32.f32 " \
        "{%0,%1,%2,%3}, {%4,%5,%6,%7}, {%8,%9}, {%0,%1,%2,%3};" \
        : "+f"((d)[0]), "+f"((d)[1]), "+f"((d)[2]), "+f"((d)[3]) \
        : "r"(a0), "r"(a1), "r"(a2), "r"(a3), "r"(b0), "r"(b1))

__device__ __forceinline__ float rna_tf32(float x) {
    float r; asm("cvt.rna.tf32.f32 %0, %1;" : "=f"(r) : "f"(x)); return r;
}

// ===== precompute: split fp32 into hi/lo tf32 parts (both RNA-rounded) =====
__global__ void fg_split_kernel(const float* __restrict__ src,
                                float* __restrict__ hi, float* __restrict__ lo, int n)
{
    int i = blockIdx.x * blockDim.x + threadIdx.x;
    if (i < n) {
        float x = src[i];
        float h = rna_tf32(x);
        hi[i] = h;
        lo[i] = rna_tf32(x - h);
    }
}

// ======================================================================
// 3xTF32 MMA kernel. 256 threads = 8 warps: wm = wid>>2 (M half),
// wn = wid&3 (text within group of 4). Warp tile: (MROWS/2) x 80.
// grid = (96 images, 24 text groups). mt = m-tile id, valid = valid rows.
// ======================================================================
template <int MROWS>
__global__ __launch_bounds__(256, 1) void fg_mma_kernel(int mt, int valid)
{
    constexpr int MW   = MROWS / 2;       // rows per M-warp (64 or 48)
    constexpr int MF   = MW / 16;         // 4 or 3
    constexpr int A_SZ = MROWS * ROWB;
    constexpr int B_SZ = NTILE * ROWB;    // 25600
    constexpr int STAGE = 2 * A_SZ + 2 * B_SZ;

    extern __shared__ char smem_raw[];
    __shared__ float swsum[8];
    __shared__ float scmax[2][G][NPAD];

    const uint32_t raw_u  = smem_u32(smem_raw);
    const uint32_t tile_u = (raw_u + 1023u) & ~1023u;

    const int tid = threadIdx.x;
    const int wid = tid >> 5;
    const int lid = tid & 31;
    const int wm = wid >> 2;          // 0..1
    const int wn = wid & 3;           // 0..3 (text)
    const int g  = lid >> 3;
    const int r  = lid & 7;

    const int bimg = blockIdx.x;
    const int cg   = blockIdx.y;

    const size_t Abase = ((size_t)bimg * NQ + mt * 128) * DIM;
    const size_t Tbase = (size_t)(cg * G) * NR * DIM;

    float acc[MF][10][4];
#pragma unroll
    for (int mf = 0; mf < MF; ++mf)
#pragma unroll
        for (int fn = 0; fn < 10; ++fn)
#pragma unroll
            for (int c = 0; c < 4; ++c) acc[mf][fn][c] = 0.0f;

    // ---------------- staging ----------------
    auto stage = [&](int ci, int buf) {
        const int k0 = ci * KC;
        const uint32_t base = tile_u + buf * STAGE;
        // A: MROWS rows x 4 chunks x {hi,lo}
#pragma unroll
        for (int i = 0; i < (MROWS * 8) / 256; ++i) {
            int idx = tid + i * 256;
            int arr = (idx >= MROWS * 4) ? 1 : 0;
            int rem = idx - arr * MROWS * 4;
            int row = rem >> 2, u = rem & 3;
            int crow = row < valid ? row : 0;
            const float* sp = (arr ? g_img_lo : g_img_hi) + Abase + (size_t)crow * DIM + k0 + u * 4;
            uint32_t sz = (row < valid) ? 16u : 0u;
            uint32_t sa = base + arr * A_SZ + row * ROWB + u * 16;
            CP_ASYNC16(sa, sp, sz);
        }
        // B: 320 rows x 4 chunks x {hi,lo}
#pragma unroll
        for (int i = 0; i < 10; ++i) {
            int idx = tid + i * 256;
            int arr = (idx >= 1280) ? 1 : 0;
            int rem = idx - arr * 1280;
            int row = rem >> 2, u = rem & 3;
            int tg = row / NPAD, rr = row - tg * NPAD;
            int crr = rr < NR ? rr : 0;
            const float* sp = (arr ? g_txt_lo : g_txt_hi) + Tbase + ((size_t)tg * NR + crr) * DIM + k0 + u * 4;
            uint32_t sz = (rr < NR) ? 16u : 0u;
            uint32_t sa = base + 2 * A_SZ + arr * B_SZ + row * ROWB + u * 16;
            CP_ASYNC16(sa, sp, sz);
        }
        CP_COMMIT();
    };

    stage(0, 0);
    stage(1, 1);
    stage(2, 2);

    // per-lane ldmatrix row offsets
    const uint32_t a_row = (uint32_t)((wm * MW + (g & 1) * 8 + r) * ROWB);
    const int      a_ub  = g >> 1;
    const uint32_t b_row = (uint32_t)((wn * NPAD + (g >> 1) * 8 + r) * ROWB);
    const int      b_ub  = g & 1;

    // ---------------- main loop ----------------
    for (int ci = 0; ci < NCHUNK; ++ci) {
        const int buf = ci % 3;
        CP_WAIT2();
        __syncthreads();

        const uint32_t sA = tile_u + buf * STAGE;
        const uint32_t sB = sA + 2 * A_SZ;

#pragma unroll
        for (int ks = 0; ks < 2; ++ks) {
            uint32_t ah[MF][4], al[MF][4];
            const uint32_t a_ch = (uint32_t)((ks * 2 + a_ub) * 16);
#pragma unroll
            for (int mf = 0; mf < MF; ++mf) {
                uint32_t ad = sA + a_row + (uint32_t)(mf * 16 * ROWB) + a_ch;
                LDSM_X4(ah[mf][0], ah[mf][1], ah[mf][2], ah[mf][3], ad);
                LDSM_X4(al[mf][0], al[mf][1], al[mf][2], al[mf][3], ad + A_SZ);
            }
            const uint32_t b_ch = (uint32_t)((ks * 2 + b_ub) * 16);
#pragma unroll
            for (int p = 0; p < 5; ++p) {
                uint32_t bh[4], bl[4];
                uint32_t bd = sB + b_row + (uint32_t)(p * 16 * ROWB) + b_ch;
                LDSM_X4(bh[0], bh[1], bh[2], bh[3], bd);
                LDSM_X4(bl[0], bl[1], bl[2], bl[3], bd + B_SZ);
#pragma unroll
                for (int mf = 0; mf < MF; ++mf) {
                    MMA_TF32(acc[mf][2 * p],     ah[mf][0], ah[mf][1], ah[mf][2], ah[mf][3], bh[0], bh[1]);
                    MMA_TF32(acc[mf][2 * p],     ah[mf][0], ah[mf][1], ah[mf][2], ah[mf][3], bl[0], bl[1]);
                    MMA_TF32(acc[mf][2 * p],     al[mf][0], al[mf][1], al[mf][2], al[mf][3], bh[0], bh[1]);
                    MMA_TF32(acc[mf][2 * p + 1], ah[mf][0], ah[mf][1], ah[mf][2], ah[mf][3], bh[2], bh[3]);
                    MMA_TF32(acc[mf][2 * p + 1], ah[mf][0], ah[mf][1], ah[mf][2], ah[mf][3], bl[2], bl[3]);
                    MMA_TF32(acc[mf][2 * p + 1], al[mf][0], al[mf][1], al[mf][2], al[mf][3], bh[2], bh[3]);
                }
            }
        }

        __syncthreads();
        if (ci + 3 < NCHUNK) stage(ci + 3, buf);
        else                 CP_COMMIT();
    }

    // ---------------- epilogue ----------------
    // acc (mf, fn, c): row_l = wm*MW + mf*16 + (c>=2)*8 + lid/4
    //                  col   = fn*8 + 2*(lid&3) + (c&1)  (within text wn)
    const int q4 = lid >> 2;
    const int c0base = 2 * (lid & 3);

    float rowsum = 0.0f;
#pragma unroll
    for (int mf = 0; mf < MF; ++mf) {
#pragma unroll
        for (int h = 0; h < 2; ++h) {
            float m = -INFINITY;
#pragma unroll
            for (int fn = 0; fn < 10; ++fn) {
                int c0 = fn * 8 + c0base;
                if (c0 < NR)     m = fmaxf(m, acc[mf][fn][h * 2 + 0]);
                if (c0 + 1 < NR) m = fmaxf(m, acc[mf][fn][h * 2 + 1]);
            }
            m = fmaxf(m, __shfl_xor_sync(0xFFFFFFFFu, m, 1));
            m = fmaxf(m, __shfl_xor_sync(0xFFFFFFFFu, m, 2));
            int row_l = wm * MW + mf * 16 + h * 8 + q4;
            if ((lid & 3) == 0 && row_l < valid) rowsum += m;
        }
    }
#pragma unroll
    for (int off = 16; off > 0; off >>= 1)
        rowsum += __shfl_xor_sync(0xFFFFFFFFu, rowsum, off);
    if (lid == 0) swsum[wid] = rowsum;

#pragma unroll
    for (int fn = 0; fn < 10; ++fn) {
#pragma unroll
        for (int cb = 0; cb < 2; ++cb) {
            float m = -INFINITY;
#pragma unroll
            for (int mf = 0; mf < MF; ++mf)
#pragma unroll
                for (int h = 0; h < 2; ++h) {
                    int row_l = wm * MW + mf * 16 + h * 8 + q4;
                    if (row_l < valid) m = fmaxf(m, acc[mf][fn][h * 2 + cb]);
                }
            m = fmaxf(m, __shfl_xor_sync(0xFFFFFFFFu, m, 4));
            m = fmaxf(m, __shfl_xor_sync(0xFFFFFFFFu, m, 8));
            m = fmaxf(m, __shfl_xor_sync(0xFFFFFFFFu, m, 16));
            if (lid < 4) scmax[wm][wn][fn * 8 + 2 * lid + cb] = m;
        }
    }
    __syncthreads();

    for (int idx = tid; idx < G * NPAD; idx += 256) {
        int wn2 = idx / NPAD, col = idx - wn2 * NPAD;
        float v = fmaxf(scmax[0][wn2][col], scmax[1][wn2][col]);
        int c = cg * G + wn2;
        g_colmax_part[(((size_t)mt * BATCH + c) * BATCH + bimg) * NPAD + col] = v;
    }
    if (tid < G) {
        g_rowsum_part[((size_t)mt * BATCH + bimg) * BATCH + cg * G + tid] =
            swsum[tid] + swsum[4 + tid];
    }
}

// ===== combine partial tiles into logit matrices =====
__global__ void fg_combine_kernel()
{
    const int c = blockIdx.x;    // 96
    const int b = threadIdx.x;   // 96
    float rs = g_rowsum_part[((size_t)0 * BATCH + b) * BATCH + c] +
               g_rowsum_part[((size_t)1 * BATCH + b) * BATCH + c];
    g_i2t[b * BATCH + c] = rs * (1.0f / NQ);

    const float* p0 = &g_colmax_part[(((size_t)0 * BATCH + c) * BATCH + b) * NPAD];
    const float* p1 = &g_colmax_part[(((size_t)1 * BATCH + c) * BATCH + b) * NPAD];
    float s = 0.f;
#pragma unroll
    for (int rr = 0; rr < NR; ++rr) s += fmaxf(p0[rr], p1[rr]);
    g_t2i[c * BATCH + b] = s * (1.0f / NR);
}

// ===== per-row cross-entropy (one warp per row, 192 rows) =====
__global__ void fg_rowce_kernel()
{
    const int wid = threadIdx.x >> 5;
    const int lid = threadIdx.x & 31;
    const int row = blockIdx.x * 32 + wid;
    if (row >= 2 * BATCH) return;
    const int label = (row < BATCH) ? row : row - BATCH;
    const float* base = (row < BATCH) ? &g_i2t[row * BATCH] : &g_t2i[(row - BATCH) * BATCH];

    float v0 = base[lid], v1 = base[lid + 32], v2 = base[lid + 64];
    float m = fmaxf(v0, fmaxf(v1, v2));
#pragma unroll
    for (int off = 16; off > 0; off >>= 1)
        m = fmaxf(m, __shfl_xor_sync(0xFFFFFFFFu, m, off));
    float s = expf(v0 - m) + expf(v1 - m) + expf(v2 - m);
#pragma unroll
    for (int off = 16; off > 0; off >>= 1)
        s += __shfl_xor_sync(0xFFFFFFFFu, s, off);
    float lse = m + logf(s);
    int slot = label >> 5, src = label & 31;
    float mine = (slot == 0) ? v0 : ((slot == 1) ? v1 : v2);
    float dval = __shfl_sync(0xFFFFFFFFu, mine, src);
    if (lid == 0) g_contrib[row] = lse - dval;
}

__global__ void fg_final_kernel(float* __restrict__ out)
{
    __shared__ float sred[192];
    const int t = threadIdx.x;
    sred[t] = g_contrib[t];
    __syncthreads();
    if (t == 0) {
        float s = 0.f;
        for (int i = 0; i < 2 * BATCH; i++) s += sred[i];
        out[0] = s * (0.5f / BATCH);
    }
}

extern "C" void kernel_launch(void* const* d_in, const int* in_sizes, int n_in,
                              void* d_out, int out_size)
{
    const float* img;
    const float* txt;
    if (in_sizes[0] > in_sizes[1]) { img = (const float*)d_in[0]; txt = (const float*)d_in[1]; }
    else                           { img = (const float*)d_in[1]; txt = (const float*)d_in[0]; }
    float* out = (float*)d_out;

    constexpr int STAGE128 = 2 * (128 * ROWB) + 2 * (NTILE * ROWB);
    constexpr int STAGE96  = 2 * (96 * ROWB)  + 2 * (NTILE * ROWB);
    constexpr int SMEM128  = 3 * STAGE128 + 1024;   // 216064
    constexpr int SMEM96   = 3 * STAGE96  + 1024;   // 200704

    static int configured = 0;
    if (!configured) {
        cudaFuncSetAttribute(fg_mma_kernel<128>, cudaFuncAttributeMaxDynamicSharedMemorySize, SMEM128);
        cudaFuncSetAttribute(fg_mma_kernel<96>,  cudaFuncAttributeMaxDynamicSharedMemorySize, SMEM96);
        configured = 1;
    }

    // hi/lo split of both inputs
    {
        float* ih; float* il; float* th; float* tl;
        cudaGetSymbolAddress((void**)&ih, g_img_hi);
        cudaGetSymbolAddress((void**)&il, g_img_lo);
        cudaGetSymbolAddress((void**)&th, g_txt_hi);
        cudaGetSymbolAddress((void**)&tl, g_txt_lo);
        int ni = BATCH * NQ * DIM, nt = BATCH * NR * DIM;
        fg_split_kernel<<<(ni + 255) / 256, 256>>>(img, ih, il, ni);
        fg_split_kernel<<<(nt + 255) / 256, 256>>>(txt, th, tl, nt);
    }

    fg_mma_kernel<128><<<dim3(BATCH, NGR), 256, SMEM128>>>(0, 128);
    fg_mma_kernel<96> <<<dim3(BATCH, NGR), 256, SMEM96>>>(1, NQ - 128);
    fg_combine_kernel<<<BATCH, BATCH>>>();
    fg_rowce_kernel<<<6, 1024>>>();
    fg_final_kernel<<<1, 192>>>(out);
}

// round 6
// speedup vs baseline: 3.6353x; 1.9221x over previous
#include <cuda_runtime.h>
#include <cuda_bf16.h>
#include <cstdint>
#include <math.h>

#define BATCH 96
#define NQ 196
#define NR 77
#define DIM 512
#define KC 32                  // k floats per chunk (bf16: 64 B data per row)
#define NCHUNK (DIM / KC)      // 16
#define G 4                    // texts per CTA
#define NGR (BATCH / G)        // 24
#define NPAD 80
#define NTILE (G * NPAD)       // 320
#define ROWB 80                // row stride bytes (64 data + 16 pad)

// ---------------- device scratch ----------------
__device__ __nv_bfloat16 g_ib0[BATCH * NQ * DIM];
__device__ __nv_bfloat16 g_ib1[BATCH * NQ * DIM];
__device__ __nv_bfloat16 g_tb0[BATCH * NR * DIM];
__device__ __nv_bfloat16 g_tb1[BATCH * NR * DIM];
__device__ float g_rowsum_part[2 * BATCH * BATCH];          // [mtile][b][c]
__device__ float g_colmax_part[2 * BATCH * BATCH * NPAD];   // [mtile][c][b][r]
__device__ float g_i2t[BATCH * BATCH];
__device__ float g_t2i[BATCH * BATCH];
__device__ float g_contrib[2 * BATCH];

// ---------------- PTX helpers (base sm_103 ISA only) ----------------
__device__ __forceinline__ uint32_t smem_u32(const void* p) {
    uint32_t a;
    asm("{ .reg .u64 t; cvta.to.shared.u64 t, %1; cvt.u32.u64 %0, t; }" : "=r"(a) : "l"(p));
    return a;
}
#define CP_ASYNC16(sa, gp, sz) \
    asm volatile("cp.async.cg.shared.global [%0], [%1], 16, %2;" \
        :: "r"(sa), "l"(gp), "r"(sz) : "memory")
#define CP_COMMIT()  asm volatile("cp.async.commit_group;" ::: "memory")
#define CP_WAIT2()   asm volatile("cp.async.wait_group 2;" ::: "memory")

#define LDSM_X4(r0, r1, r2, r3, a) \
    asm volatile("ldmatrix.sync.aligned.m8n8.x4.shared.b16 {%0,%1,%2,%3}, [%4];" \
        : "=r"(r0), "=r"(r1), "=r"(r2), "=r"(r3) : "r"(a))

#define MMA_BF16(d, a0, a1, a2, a3, b0, b1) \
    asm volatile("mma.sync.aligned.m16n8k16.row.col.f32.bf16.bf16.f32 " \
        "{%0,%1,%2,%3}, {%4,%5,%6,%7}, {%8,%9}, {%0,%1,%2,%3};" \
        : "+f"((d)[0]), "+f"((d)[1]), "+f"((d)[2]), "+f"((d)[3]) \
        : "r"(a0), "r"(a1), "r"(a2), "r"(a3), "r"(b0), "r"(b1))

// ===== precompute: split fp32 into bf16 hi (b0) and residual (b1) =====
__global__ void fg_split_kernel(const float* __restrict__ src,
                                __nv_bfloat16* __restrict__ b0,
                                __nv_bfloat16* __restrict__ b1, int n)
{
    int i = blockIdx.x * blockDim.x + threadIdx.x;
    if (i < n) {
        float x = src[i];
        __nv_bfloat16 h = __float2bfloat16(x);
        b0[i] = h;
        b1[i] = __float2bfloat16(x - __bfloat162float(h));
    }
}

// ======================================================================
// bf16x2 MMA kernel. 256 threads = 8 warps: wm = wid>>2 (M half),
// wn = wid&3 (text within group of 4). Warp tile: (MROWS/2) x 80.
// grid = (96 images, 24 text groups). mt = m-tile id, valid = valid rows.
// ======================================================================
template <int MROWS>
__global__ __launch_bounds__(256, 1) void fg_mma_kernel(int mt, int valid)
{
    constexpr int MW   = MROWS / 2;       // rows per M-warp (64 or 48)
    constexpr int MF   = MW / 16;         // 4 or 3
    constexpr int A_SZ = MROWS * ROWB;    // per part
    constexpr int B_SZ = NTILE * ROWB;    // 25600 per part
    constexpr int STAGE = 2 * A_SZ + 2 * B_SZ;

    extern __shared__ char smem_raw[];
    __shared__ float swsum[8];
    __shared__ float scmax[2][G][NPAD];

    const uint32_t raw_u  = smem_u32(smem_raw);
    const uint32_t tile_u = (raw_u + 1023u) & ~1023u;

    const int tid = threadIdx.x;
    const int wid = tid >> 5;
    const int lid = tid & 31;
    const int wm = wid >> 2;          // 0..1
    const int wn = wid & 3;           // 0..3 (text)
    const int g  = lid >> 3;
    const int r  = lid & 7;

    const int bimg = blockIdx.x;
    const int cg   = blockIdx.y;

    const size_t Abase = ((size_t)bimg * NQ + mt * 128) * DIM;
    const size_t Tbase = (size_t)(cg * G) * NR * DIM;

    float acc[MF][10][4];
#pragma unroll
    for (int mf = 0; mf < MF; ++mf)
#pragma unroll
        for (int fn = 0; fn < 10; ++fn)
#pragma unroll
            for (int c = 0; c < 4; ++c) acc[mf][fn][c] = 0.0f;

    // ---------------- staging (16B = 8 bf16 per cp.async) ----------------
    auto stage = [&](int ci, int buf) {
        const int k0 = ci * KC;
        const uint32_t base = tile_u + buf * STAGE;
        // A: MROWS rows x 4 u-slots x {b0,b1}
#pragma unroll
        for (int i = 0; i < (MROWS * 8) / 256; ++i) {
            int idx = tid + i * 256;
            int arr = (idx >= MROWS * 4) ? 1 : 0;
            int rem = idx - arr * MROWS * 4;
            int row = rem >> 2, u = rem & 3;
            int crow = row < valid ? row : 0;
            const __nv_bfloat16* sp = (arr ? g_ib1 : g_ib0) + Abase + (size_t)crow * DIM + k0 + u * 8;
            uint32_t sz = (row < valid) ? 16u : 0u;
            uint32_t sa = base + arr * A_SZ + row * ROWB + u * 16;
            CP_ASYNC16(sa, sp, sz);
        }
        // B: 320 rows x 4 u-slots x {b0,b1}
#pragma unroll
        for (int i = 0; i < 10; ++i) {
            int idx = tid + i * 256;
            int arr = (idx >= 1280) ? 1 : 0;
            int rem = idx - arr * 1280;
            int row = rem >> 2, u = rem & 3;
            int tg = row / NPAD, rr = row - tg * NPAD;
            int crr = rr < NR ? rr : 0;
            const __nv_bfloat16* sp = (arr ? g_tb1 : g_tb0) + Tbase + ((size_t)tg * NR + crr) * DIM + k0 + u * 8;
            uint32_t sz = (rr < NR) ? 16u : 0u;
            uint32_t sa = base + 2 * A_SZ + arr * B_SZ + row * ROWB + u * 16;
            CP_ASYNC16(sa, sp, sz);
        }
        CP_COMMIT();
    };

    stage(0, 0);
    stage(1, 1);
    stage(2, 2);

    // per-lane ldmatrix row offsets (same maps as validated tf32 kernel)
    const uint32_t a_row = (uint32_t)((wm * MW + (g & 1) * 8 + r) * ROWB);
    const uint32_t a_ub  = (uint32_t)(g >> 1);   // k-half within k16
    const uint32_t b_row = (uint32_t)((wn * NPAD + (g >> 1) * 8 + r) * ROWB);
    const uint32_t b_ub  = (uint32_t)(g & 1);

    // ---------------- main loop ----------------
    for (int ci = 0; ci < NCHUNK; ++ci) {
        const int buf = ci % 3;
        CP_WAIT2();
        __syncthreads();

        const uint32_t sA = tile_u + buf * STAGE;
        const uint32_t sB = sA + 2 * A_SZ;

#pragma unroll
        for (int ks = 0; ks < 2; ++ks) {
            uint32_t a0[MF][4], a1[MF][4];
            const uint32_t a_ch = (uint32_t)(ks * 32) + a_ub * 16;
#pragma unroll
            for (int mf = 0; mf < MF; ++mf) {
                uint32_t ad = sA + a_row + (uint32_t)(mf * 16 * ROWB) + a_ch;
                LDSM_X4(a0[mf][0], a0[mf][1], a0[mf][2], a0[mf][3], ad);
                LDSM_X4(a1[mf][0], a1[mf][1], a1[mf][2], a1[mf][3], ad + A_SZ);
            }
            const uint32_t b_ch = (uint32_t)(ks * 32) + b_ub * 16;
#pragma unroll
            for (int p = 0; p < 5; ++p) {
                uint32_t bh[4], bl[4];
                uint32_t bd = sB + b_row + (uint32_t)(p * 16 * ROWB) + b_ch;
                LDSM_X4(bh[0], bh[1], bh[2], bh[3], bd);
                LDSM_X4(bl[0], bl[1], bl[2], bl[3], bd + B_SZ);
#pragma unroll
                for (int mf = 0; mf < MF; ++mf) {
                    MMA_BF16(acc[mf][2 * p],     a0[mf][0], a0[mf][1], a0[mf][2], a0[mf][3], bh[0], bh[1]);
                    MMA_BF16(acc[mf][2 * p],     a0[mf][0], a0[mf][1], a0[mf][2], a0[mf][3], bl[0], bl[1]);
                    MMA_BF16(acc[mf][2 * p],     a1[mf][0], a1[mf][1], a1[mf][2], a1[mf][3], bh[0], bh[1]);
                    MMA_BF16(acc[mf][2 * p + 1], a0[mf][0], a0[mf][1], a0[mf][2], a0[mf][3], bh[2], bh[3]);
                    MMA_BF16(acc[mf][2 * p + 1], a0[mf][0], a0[mf][1], a0[mf][2], a0[mf][3], bl[2], bl[3]);
                    MMA_BF16(acc[mf][2 * p + 1], a1[mf][0], a1[mf][1], a1[mf][2], a1[mf][3], bh[2], bh[3]);
                }
            }
        }

        __syncthreads();
        if (ci + 3 < NCHUNK) stage(ci + 3, buf);
        else                 CP_COMMIT();
    }

    // ---------------- epilogue ----------------
    // acc (mf, fn, c): row_l = wm*MW + mf*16 + (c>=2)*8 + lid/4
    //                  col   = fn*8 + 2*(lid&3) + (c&1)  (within text wn)
    const int q4 = lid >> 2;
    const int c0base = 2 * (lid & 3);

    float rowsum = 0.0f;
#pragma unroll
    for (int mf = 0; mf < MF; ++mf) {
#pragma unroll
        for (int h = 0; h < 2; ++h) {
            float m = -INFINITY;
#pragma unroll
            for (int fn = 0; fn < 10; ++fn) {
                int c0 = fn * 8 + c0base;
                if (c0 < NR)     m = fmaxf(m, acc[mf][fn][h * 2 + 0]);
                if (c0 + 1 < NR) m = fmaxf(m, acc[mf][fn][h * 2 + 1]);
            }
            m = fmaxf(m, __shfl_xor_sync(0xFFFFFFFFu, m, 1));
            m = fmaxf(m, __shfl_xor_sync(0xFFFFFFFFu, m, 2));
            int row_l = wm * MW + mf * 16 + h * 8 + q4;
            if ((lid & 3) == 0 && row_l < valid) rowsum += m;
        }
    }
#pragma unroll
    for (int off = 16; off > 0; off >>= 1)
        rowsum += __shfl_xor_sync(0xFFFFFFFFu, rowsum, off);
    if (lid == 0) swsum[wid] = rowsum;

#pragma unroll
    for (int fn = 0; fn < 10; ++fn) {
#pragma unroll
        for (int cb = 0; cb < 2; ++cb) {
            float m = -INFINITY;
#pragma unroll
            for (int mf = 0; mf < MF; ++mf)
#pragma unroll
                for (int h = 0; h < 2; ++h) {
                    int row_l = wm * MW + mf * 16 + h * 8 + q4;
                    if (row_l < valid) m = fmaxf(m, acc[mf][fn][h * 2 + cb]);
                }
            m = fmaxf(m, __shfl_xor_sync(0xFFFFFFFFu, m, 4));
            m = fmaxf(m, __shfl_xor_sync(0xFFFFFFFFu, m, 8));
            m = fmaxf(m, __shfl_xor_sync(0xFFFFFFFFu, m, 16));
            if (lid < 4) scmax[wm][wn][fn * 8 + 2 * lid + cb] = m;
        }
    }
    __syncthreads();

    for (int idx = tid; idx < G * NPAD; idx += 256) {
        int wn2 = idx / NPAD, col = idx - wn2 * NPAD;
        float v = fmaxf(scmax[0][wn2][col], scmax[1][wn2][col]);
        int c = cg * G + wn2;
        g_colmax_part[(((size_t)mt * BATCH + c) * BATCH + bimg) * NPAD + col] = v;
    }
    if (tid < G) {
        g_rowsum_part[((size_t)mt * BATCH + bimg) * BATCH + cg * G + tid] =
            swsum[tid] + swsum[4 + tid];
    }
}

// ===== combine partial tiles into logit matrices =====
__global__ void fg_combine_kernel()
{
    const int c = blockIdx.x;    // 96
    const int b = threadIdx.x;   // 96
    float rs = g_rowsum_part[((size_t)0 * BATCH + b) * BATCH + c] +
               g_rowsum_part[((size_t)1 * BATCH + b) * BATCH + c];
    g_i2t[b * BATCH + c] = rs * (1.0f / NQ);

    const float* p0 = &g_colmax_part[(((size_t)0 * BATCH + c) * BATCH + b) * NPAD];
    const float* p1 = &g_colmax_part[(((size_t)1 * BATCH + c) * BATCH + b) * NPAD];
    float s = 0.f;
#pragma unroll
    for (int rr = 0; rr < NR; ++rr) s += fmaxf(p0[rr], p1[rr]);
    g_t2i[c * BATCH + b] = s * (1.0f / NR);
}

// ===== per-row cross-entropy (one warp per row, 192 rows) =====
__global__ void fg_rowce_kernel()
{
    const int wid = threadIdx.x >> 5;
    const int lid = threadIdx.x & 31;
    const int row = blockIdx.x * 32 + wid;
    if (row >= 2 * BATCH) return;
    const int label = (row < BATCH) ? row : row - BATCH;
    const float* base = (row < BATCH) ? &g_i2t[row * BATCH] : &g_t2i[(row - BATCH) * BATCH];

    float v0 = base[lid], v1 = base[lid + 32], v2 = base[lid + 64];
    float m = fmaxf(v0, fmaxf(v1, v2));
#pragma unroll
    for (int off = 16; off > 0; off >>= 1)
        m = fmaxf(m, __shfl_xor_sync(0xFFFFFFFFu, m, off));
    float s = expf(v0 - m) + expf(v1 - m) + expf(v2 - m);
#pragma unroll
    for (int off = 16; off > 0; off >>= 1)
        s += __shfl_xor_sync(0xFFFFFFFFu, s, off);
    float lse = m + logf(s);
    int slot = label >> 5, src = label & 31;
    float mine = (slot == 0) ? v0 : ((slot == 1) ? v1 : v2);
    float dval = __shfl_sync(0xFFFFFFFFu, mine, src);
    if (lid == 0) g_contrib[row] = lse - dval;
}

__global__ void fg_final_kernel(float* __restrict__ out)
{
    __shared__ float sred[192];
    const int t = threadIdx.x;
    sred[t] = g_contrib[t];
    __syncthreads();
    if (t == 0) {
        float s = 0.f;
        for (int i = 0; i < 2 * BATCH; i++) s += sred[i];
        out[0] = s * (0.5f / BATCH);
    }
}

extern "C" void kernel_launch(void* const* d_in, const int* in_sizes, int n_in,
                              void* d_out, int out_size)
{
    const float* img;
    const float* txt;
    if (in_sizes[0] > in_sizes[1]) { img = (const float*)d_in[0]; txt = (const float*)d_in[1]; }
    else                           { img = (const float*)d_in[1]; txt = (const float*)d_in[0]; }
    float* out = (float*)d_out;

    constexpr int STAGE128 = 2 * (128 * ROWB) + 2 * (NTILE * ROWB);
    constexpr int STAGE96  = 2 * (96 * ROWB)  + 2 * (NTILE * ROWB);
    constexpr int SMEM128  = 3 * STAGE128 + 1024;   // 216064
    constexpr int SMEM96   = 3 * STAGE96  + 1024;   // 200704

    static int configured = 0;
    if (!configured) {
        cudaFuncSetAttribute(fg_mma_kernel<128>, cudaFuncAttributeMaxDynamicSharedMemorySize, SMEM128);
        cudaFuncSetAttribute(fg_mma_kernel<96>,  cudaFuncAttributeMaxDynamicSharedMemorySize, SMEM96);
        configured = 1;
    }

    // bf16 hi/lo split of both inputs
    {
        __nv_bfloat16 *ib0, *ib1, *tb0, *tb1;
        cudaGetSymbolAddress((void**)&ib0, g_ib0);
        cudaGetSymbolAddress((void**)&ib1, g_ib1);
        cudaGetSymbolAddress((void**)&tb0, g_tb0);
        cudaGetSymbolAddress((void**)&tb1, g_tb1);
        int ni = BATCH * NQ * DIM, nt = BATCH * NR * DIM;
        fg_split_kernel<<<(ni + 255) / 256, 256>>>(img, ib0, ib1, ni);
        fg_split_kernel<<<(nt + 255) / 256, 256>>>(txt, tb0, tb1, nt);
    }

    fg_mma_kernel<128><<<dim3(BATCH, NGR), 256, SMEM128>>>(0, 128);
    fg_mma_kernel<96> <<<dim3(BATCH, NGR), 256, SMEM96>>>(1, NQ - 128);
    fg_combine_kernel<<<BATCH, BATCH>>>();
    fg_rowce_kernel<<<6, 1024>>>();
    fg_final_kernel<<<1, 192>>>(out);
}